// round 3
// baseline (speedup 1.0000x reference)
#include <cuda_runtime.h>

// SLAM_Layer: fused 3-GEMM-per-timestep kernel, fp32 CUDA-core baseline.
//   H_t = relu(x_aux[:,t,:] @ W1 + b1)        (128x128, K=64)
//   S_t = H_t @ W2 + b2                       (128x128, K=128)
//   out_t = x_main[3,t,0] @ S_t               (128x128, K=128)
// One block per t (1024 blocks), 256 threads, 8x8 register tile per thread.

#define TPB 256

__global__ __launch_bounds__(TPB, 1)
void slam_kernel(const float* __restrict__ x_main,
                 const float* __restrict__ x_aux,
                 const float* __restrict__ gW1,
                 const float* __restrict__ gb1,
                 const float* __restrict__ gW2,
                 const float* __restrict__ gb2,
                 float* __restrict__ out)
{
    constexpr int T = 1024, M = 128, A = 64, D = 128;

    extern __shared__ float smem[];
    float* sW = smem;            // 16384 floats (64KB): W1 -> W2 -> main
    float* sH = smem + 16384;    // 16384 floats: H
    float* sS = smem + 32768;    // 16384 floats: S (aliases X region)
    float* sX = sS;              // X = x_aux[:,t,:] (128x64), dead before S is written
    __shared__ float sB1[D];
    __shared__ float sB2[M];

    const int t   = blockIdx.x;
    const int tid = threadIdx.x;
    const int tx = tid & 15, ty = tid >> 4;
    const int row0 = ty * 8, col0 = tx * 8;

    if (tid < 128) { sB1[tid] = gb1[tid]; sB2[tid] = gb2[tid]; }

    // Load W1 (64x128 = 2048 float4)
    {
        const float4* src = (const float4*)gW1;
        float4* dst = (float4*)sW;
        #pragma unroll
        for (int i = 0; i < 8; ++i) dst[tid + i * TPB] = src[tid + i * TPB];
    }
    // Load X: row m is 64 contiguous floats at x_aux + (m*T + t)*A
    {
        float4* dst = (float4*)sX;
        #pragma unroll
        for (int i = 0; i < 8; ++i) {
            int e = tid + i * TPB;
            int m = e >> 4, c = e & 15;
            dst[e] = ((const float4*)(x_aux + ((size_t)m * T + t) * A))[c];
        }
    }
    __syncthreads();

    float acc[8][8];
    float a[8], b[8];

    // ---------------- Phase 1: H = relu(X @ W1 + b1), K = 64 ----------------
    #pragma unroll
    for (int r = 0; r < 8; ++r)
        #pragma unroll
        for (int c = 0; c < 8; ++c) acc[r][c] = 0.f;

    #pragma unroll 4
    for (int k = 0; k < A; ++k) {
        #pragma unroll
        for (int r = 0; r < 8; ++r) a[r] = sX[(row0 + r) * A + k];
        float4 bv0 = *(const float4*)&sW[k * D + col0];
        float4 bv1 = *(const float4*)&sW[k * D + col0 + 4];
        b[0]=bv0.x; b[1]=bv0.y; b[2]=bv0.z; b[3]=bv0.w;
        b[4]=bv1.x; b[5]=bv1.y; b[6]=bv1.z; b[7]=bv1.w;
        #pragma unroll
        for (int r = 0; r < 8; ++r)
            #pragma unroll
            for (int c = 0; c < 8; ++c) acc[r][c] = fmaf(a[r], b[c], acc[r][c]);
    }

    // Epilogue: bias + relu -> sH
    #pragma unroll
    for (int r = 0; r < 8; ++r) {
        float4 v0, v1;
        v0.x = fmaxf(acc[r][0] + sB1[col0 + 0], 0.f);
        v0.y = fmaxf(acc[r][1] + sB1[col0 + 1], 0.f);
        v0.z = fmaxf(acc[r][2] + sB1[col0 + 2], 0.f);
        v0.w = fmaxf(acc[r][3] + sB1[col0 + 3], 0.f);
        v1.x = fmaxf(acc[r][4] + sB1[col0 + 4], 0.f);
        v1.y = fmaxf(acc[r][5] + sB1[col0 + 5], 0.f);
        v1.z = fmaxf(acc[r][6] + sB1[col0 + 6], 0.f);
        v1.w = fmaxf(acc[r][7] + sB1[col0 + 7], 0.f);
        *(float4*)&sH[(row0 + r) * D + col0]     = v0;
        *(float4*)&sH[(row0 + r) * D + col0 + 4] = v1;
    }
    __syncthreads();   // everyone done reading W1/X, sH fully written

    // Load W2 (128x128 = 4096 float4) over W1
    {
        const float4* src = (const float4*)gW2;
        float4* dst = (float4*)sW;
        #pragma unroll
        for (int i = 0; i < 16; ++i) dst[tid + i * TPB] = src[tid + i * TPB];
    }
    __syncthreads();

    // ---------------- Phase 2: S = H @ W2 + b2, K = 128 ----------------
    #pragma unroll
    for (int r = 0; r < 8; ++r)
        #pragma unroll
        for (int c = 0; c < 8; ++c) acc[r][c] = 0.f;

    #pragma unroll 4
    for (int k = 0; k < D; ++k) {
        #pragma unroll
        for (int r = 0; r < 8; ++r) a[r] = sH[(row0 + r) * D + k];
        float4 bv0 = *(const float4*)&sW[k * M + col0];
        float4 bv1 = *(const float4*)&sW[k * M + col0 + 4];
        b[0]=bv0.x; b[1]=bv0.y; b[2]=bv0.z; b[3]=bv0.w;
        b[4]=bv1.x; b[5]=bv1.y; b[6]=bv1.z; b[7]=bv1.w;
        #pragma unroll
        for (int r = 0; r < 8; ++r)
            #pragma unroll
            for (int c = 0; c < 8; ++c) acc[r][c] = fmaf(a[r], b[c], acc[r][c]);
    }

    // Epilogue: + b2 -> sS (overwrites dead X region)
    #pragma unroll
    for (int r = 0; r < 8; ++r) {
        float4 v0, v1;
        v0.x = acc[r][0] + sB2[col0 + 0];
        v0.y = acc[r][1] + sB2[col0 + 1];
        v0.z = acc[r][2] + sB2[col0 + 2];
        v0.w = acc[r][3] + sB2[col0 + 3];
        v1.x = acc[r][4] + sB2[col0 + 4];
        v1.y = acc[r][5] + sB2[col0 + 5];
        v1.z = acc[r][6] + sB2[col0 + 6];
        v1.w = acc[r][7] + sB2[col0 + 7];
        *(float4*)&sS[(row0 + r) * M + col0]     = v0;
        *(float4*)&sS[(row0 + r) * M + col0 + 4] = v1;
    }
    __syncthreads();   // done reading W2/H, sS fully written

    // Load main tile x_main[3, t, 0] (128x128 contiguous) over W2
    {
        const float4* src = (const float4*)(x_main + ((size_t)(3 * T + t)) * (M * M));
        float4* dst = (float4*)sW;
        #pragma unroll
        for (int i = 0; i < 16; ++i) dst[tid + i * TPB] = src[tid + i * TPB];
    }
    __syncthreads();

    // ---------------- Phase 3: out_t = main @ S, K = 128 ----------------
    #pragma unroll
    for (int r = 0; r < 8; ++r)
        #pragma unroll
        for (int c = 0; c < 8; ++c) acc[r][c] = 0.f;

    #pragma unroll 4
    for (int k = 0; k < M; ++k) {
        #pragma unroll
        for (int r = 0; r < 8; ++r) a[r] = sW[(row0 + r) * M + k];
        float4 bv0 = *(const float4*)&sS[k * M + col0];
        float4 bv1 = *(const float4*)&sS[k * M + col0 + 4];
        b[0]=bv0.x; b[1]=bv0.y; b[2]=bv0.z; b[3]=bv0.w;
        b[4]=bv1.x; b[5]=bv1.y; b[6]=bv1.z; b[7]=bv1.w;
        #pragma unroll
        for (int r = 0; r < 8; ++r)
            #pragma unroll
            for (int c = 0; c < 8; ++c) acc[r][c] = fmaf(a[r], b[c], acc[r][c]);
    }

    // Epilogue: write out[t, i, k]
    float* outT = out + (size_t)t * (M * M);
    #pragma unroll
    for (int r = 0; r < 8; ++r) {
        float4 v0, v1;
        v0.x = acc[r][0]; v0.y = acc[r][1]; v0.z = acc[r][2]; v0.w = acc[r][3];
        v1.x = acc[r][4]; v1.y = acc[r][5]; v1.z = acc[r][6]; v1.w = acc[r][7];
        *(float4*)&outT[(row0 + r) * M + col0]     = v0;
        *(float4*)&outT[(row0 + r) * M + col0 + 4] = v1;
    }
}

extern "C" void kernel_launch(void* const* d_in, const int* in_sizes, int n_in,
                              void* d_out, int out_size)
{
    const float* x_main = (const float*)d_in[0];
    const float* x_aux  = (const float*)d_in[1];
    const float* W1     = (const float*)d_in[2];
    const float* b1     = (const float*)d_in[3];
    const float* W2     = (const float*)d_in[4];
    const float* b2     = (const float*)d_in[5];
    float* out = (float*)d_out;

    const int smem_bytes = 3 * 16384 * sizeof(float);  // 192 KB dynamic
    cudaFuncSetAttribute(slam_kernel, cudaFuncAttributeMaxDynamicSharedMemorySize, smem_bytes);
    slam_kernel<<<1024, TPB, smem_bytes>>>(x_main, x_aux, W1, b1, W2, b2, out);
}

// round 7
// speedup vs baseline: 2.7837x; 2.7837x over previous
#include <cuda_runtime.h>
#include <cuda_bf16.h>
#include <stdint.h>

// SLAM_Layer: fused per-t 3-GEMM chain on mma.sync (bf16 HMMA), 2-term bf16 split.
//   Phase1: H   = relu(X_t @ W1 + b1)      D1[m][d], M=128 K=64  N=128
//   Phase2: S^T = W2^T @ H^T (+b2)         D2[k][m], M=128 K=128 N=128
//   Phase3: out = main_t @ S               D3[i][k], M=128 K=128 N=128 (B = S^T)
// All operands K-major in swizzled SMEM. One block per t, 8 warps, warp tile 32x64.

#define TPB 256
static constexpr int Tn = 1024;

// dynamic smem byte offsets
static constexpr uint32_t OFF_XHI   = 0;        // 16KB
static constexpr uint32_t OFF_XLO   = 16384;
static constexpr uint32_t OFF_W1THI = 32768;
static constexpr uint32_t OFF_W1TLO = 49152;
static constexpr uint32_t OFF_HHI   = 0;        // 32KB (over X/W1T after phase1)
static constexpr uint32_t OFF_HLO   = 32768;
static constexpr uint32_t OFF_W2THI = 65536;    // 32KB
static constexpr uint32_t OFF_W2TLO = 98304;
static constexpr uint32_t OFF_STHI  = 65536;    // over W2T after phase2
static constexpr uint32_t OFF_STLO  = 98304;
static constexpr uint32_t OFF_MHI   = 131072;   // 32KB
static constexpr uint32_t OFF_MLO   = 163840;
static constexpr uint32_t OFF_OUT   = 131072;   // fp32 staging (stride 132), over M in epi3
static constexpr uint32_t DYN_BYTES = 131072 + 132 * 128 * 4 + 1024;  // 199,680

__device__ __forceinline__ uint32_t smem_u32(const void* p) {
    uint32_t a;
    asm("{ .reg .u64 t; cvta.to.shared.u64 t, %1; cvt.u32.u64 %0, t; }" : "=r"(a) : "l"(p));
    return a;
}

// SW128-style swizzle (writer and reader share these, so they only affect banks)
__device__ __forceinline__ uint32_t swz(uint32_t b) { return b ^ ((b >> 3) & 0x70); }
__device__ __forceinline__ uint32_t k64_off(int r, int c) {   // 128 rows x 64 bf16
    return swz((uint32_t)(r * 128 + c * 2));
}
__device__ __forceinline__ uint32_t k128_off(int r, int c) {  // 128 rows x 128 bf16
    return swz(((uint32_t)(c >> 6) << 14) + ((uint32_t)(r >> 3) << 10) +
               ((uint32_t)(r & 7) << 7) + ((uint32_t)(c & 63) << 1));
}

__device__ __forceinline__ void split_bf(float f, __nv_bfloat16& h, __nv_bfloat16& l) {
    h = __float2bfloat16_rn(f);
    l = __float2bfloat16_rn(f - __bfloat162float(h));
}
__device__ __forceinline__ void store_pair(uint8_t* base, uint32_t off,
                                           __nv_bfloat16 a, __nv_bfloat16 b) {
    __nv_bfloat162 v; v.x = a; v.y = b;
    *(__nv_bfloat162*)(base + off) = v;
}

#define LDSM4(r, addr)                                                          \
    asm volatile("ldmatrix.sync.aligned.m8n8.x4.shared.b16 {%0,%1,%2,%3}, [%4];"\
        : "=r"((r)[0]), "=r"((r)[1]), "=r"((r)[2]), "=r"((r)[3]) : "r"(addr))

#define MMA16816(d, a, b0, b1)                                                  \
    asm volatile("mma.sync.aligned.m16n8k16.row.col.f32.bf16.bf16.f32 "         \
        "{%0,%1,%2,%3}, {%4,%5,%6,%7}, {%8,%9}, {%0,%1,%2,%3};"                 \
        : "+f"((d)[0]), "+f"((d)[1]), "+f"((d)[2]), "+f"((d)[3])                \
        : "r"((a)[0]), "r"((a)[1]), "r"((a)[2]), "r"((a)[3]), "r"(b0), "r"(b1))

// One phase: D += sum over 3 split terms of A @ B^T (A rows x K, B rows x K, K-major).
// Warp tile: rows [32*wr, 32*wr+32), cols [64*wc, 64*wc+64).
template <int NK, bool K64>
__device__ __forceinline__ void gemm_phase(uint32_t sbase,
                                           uint32_t aHi, uint32_t aLo,
                                           uint32_t bHi, uint32_t bLo,
                                           int wr, int wc, int lane,
                                           float d[2][8][4]) {
    const int a_row = lane & 15, a_qp = lane >> 4;                 // A x4 lane mapping
    const int b_row = ((lane >> 4) << 3) + (lane & 7);             // B x4 lane mapping
    const int b_qp  = (lane >> 3) & 1;

    #pragma unroll 1
    for (int term = 0; term < 3; ++term) {
        const uint32_t Ab = sbase + ((term == 2) ? aLo : aHi);
        const uint32_t Bb = sbase + ((term == 1) ? bLo : bHi);
        #pragma unroll
        for (int ks = 0; ks < NK; ++ks) {
            uint32_t a[2][4];
            #pragma unroll
            for (int mi = 0; mi < 2; ++mi) {
                int r = 32 * wr + 16 * mi + a_row;
                int c = (2 * ks + a_qp) * 8;
                uint32_t addr = Ab + (K64 ? k64_off(r, c) : k128_off(r, c));
                LDSM4(a[mi], addr);
            }
            #pragma unroll
            for (int nb = 0; nb < 4; ++nb) {
                uint32_t b[4];
                int r = 64 * wc + 16 * nb + b_row;
                int c = (2 * ks + b_qp) * 8;
                uint32_t addr = Bb + (K64 ? k64_off(r, c) : k128_off(r, c));
                LDSM4(b, addr);
                #pragma unroll
                for (int mi = 0; mi < 2; ++mi) {
                    MMA16816(d[mi][2 * nb],     a[mi], b[0], b[1]);
                    MMA16816(d[mi][2 * nb + 1], a[mi], b[2], b[3]);
                }
            }
        }
    }
}

__global__ __launch_bounds__(TPB, 1)
void slam_mma(const float* __restrict__ x_main, const float* __restrict__ x_aux,
              const float* __restrict__ gW1, const float* __restrict__ gb1,
              const float* __restrict__ gW2, const float* __restrict__ gb2,
              float* __restrict__ out)
{
    extern __shared__ uint8_t dynraw[];
    __shared__ float sB1[128], sB2[128];

    uint8_t* dyn = (uint8_t*)(((uintptr_t)dynraw + 1023) & ~(uintptr_t)1023);
    const uint32_t sbase = smem_u32(dyn);
    const int t = blockIdx.x;
    const int tid = threadIdx.x, wid = tid >> 5, lane = tid & 31;
    const int wr = wid >> 1, wc = wid & 1;   // 4 row-groups x 2 col-groups

    if (tid < 128) { sB1[tid] = gb1[tid]; sB2[tid] = gb2[tid]; }

    // ---- global loads + bf16 split into SMEM tiles ----
    // X_t: row m = 64 floats at x_aux + (m*T + t)*64
    #pragma unroll
    for (int i = 0; i < 8; i++) {
        int idx = tid + i * TPB;            // 2048 float4
        int m = idx >> 4, c = (idx & 15) * 4;
        float4 v = *(const float4*)(x_aux + ((size_t)m * Tn + t) * 64 + c);
        __nv_bfloat16 h0,l0,h1,l1,h2,l2,h3,l3;
        split_bf(v.x,h0,l0); split_bf(v.y,h1,l1); split_bf(v.z,h2,l2); split_bf(v.w,h3,l3);
        store_pair(dyn, OFF_XHI + k64_off(m, c),     h0, h1);
        store_pair(dyn, OFF_XHI + k64_off(m, c + 2), h2, h3);
        store_pair(dyn, OFF_XLO + k64_off(m, c),     l0, l1);
        store_pair(dyn, OFF_XLO + k64_off(m, c + 2), l2, l3);
    }
    // W1^T: gW1[a*128+d] -> tile row d, col a
    #pragma unroll
    for (int i = 0; i < 32; i++) {
        int idx = tid + i * TPB;            // 8192
        int a = idx >> 7, dcol = idx & 127;
        __nv_bfloat16 h, l; split_bf(gW1[idx], h, l);
        *(__nv_bfloat16*)(dyn + OFF_W1THI + k64_off(dcol, a)) = h;
        *(__nv_bfloat16*)(dyn + OFF_W1TLO + k64_off(dcol, a)) = l;
    }
    // W2^T: gW2[d*128+k] -> tile row k, col d
    #pragma unroll
    for (int i = 0; i < 64; i++) {
        int idx = tid + i * TPB;            // 16384
        int drow = idx >> 7, k = idx & 127;
        __nv_bfloat16 h, l; split_bf(gW2[idx], h, l);
        *(__nv_bfloat16*)(dyn + OFF_W2THI + k128_off(k, drow)) = h;
        *(__nv_bfloat16*)(dyn + OFF_W2TLO + k128_off(k, drow)) = l;
    }
    // main_t = x_main[3, t, 0]: natural [i][j]
    {
        const float* mp = x_main + ((size_t)(3 * Tn + t)) * 16384;
        #pragma unroll
        for (int i = 0; i < 16; i++) {
            int idx = tid + i * TPB;        // 4096 float4
            int r = idx >> 5, c = (idx & 31) * 4;
            float4 v = *(const float4*)(mp + r * 128 + c);
            __nv_bfloat16 h0,l0,h1,l1,h2,l2,h3,l3;
            split_bf(v.x,h0,l0); split_bf(v.y,h1,l1); split_bf(v.z,h2,l2); split_bf(v.w,h3,l3);
            store_pair(dyn, OFF_MHI + k128_off(r, c),     h0, h1);
            store_pair(dyn, OFF_MHI + k128_off(r, c + 2), h2, h3);
            store_pair(dyn, OFF_MLO + k128_off(r, c),     l0, l1);
            store_pair(dyn, OFF_MLO + k128_off(r, c + 2), l2, l3);
        }
    }
    __syncthreads();

    const int r_base = lane >> 2;             // D frag: rows r_base / r_base+8
    const int c_base = 2 * (lane & 3);        // cols c_base, c_base+1

    float d[2][8][4];

    // ---------------- Phase 1: D1[m][d] = X @ W1 ----------------
    #pragma unroll
    for (int mi = 0; mi < 2; ++mi)
        #pragma unroll
        for (int nj = 0; nj < 8; ++nj)
            #pragma unroll
            for (int q = 0; q < 4; ++q) d[mi][nj][q] = 0.f;

    gemm_phase<4, true>(sbase, OFF_XHI, OFF_XLO, OFF_W1THI, OFF_W1TLO, wr, wc, lane, d);
    __syncthreads();   // all warps done reading X/W1T before H overwrites them

    // Epilogue 1: +b1, relu, split -> H
    #pragma unroll
    for (int mi = 0; mi < 2; ++mi) {
        #pragma unroll
        for (int nj = 0; nj < 8; ++nj) {
            int col = 64 * wc + 8 * nj + c_base;
            float bx = sB1[col], by = sB1[col + 1];
            #pragma unroll
            for (int h = 0; h < 2; ++h) {   // h=0: rows r_base, h=1: +8
                int row = 32 * wr + 16 * mi + r_base + 8 * h;
                float f0 = fmaxf(d[mi][nj][2 * h]     + bx, 0.f);
                float f1 = fmaxf(d[mi][nj][2 * h + 1] + by, 0.f);
                __nv_bfloat16 h0,l0,h1,l1; split_bf(f0,h0,l0); split_bf(f1,h1,l1);
                store_pair(dyn, OFF_HHI + k128_off(row, col), h0, h1);
                store_pair(dyn, OFF_HLO + k128_off(row, col), l0, l1);
            }
        }
    }
    __syncthreads();

    // ---------------- Phase 2: D2[k][m] = W2^T @ H^T = S^T ----------------
    #pragma unroll
    for (int mi = 0; mi < 2; ++mi)
        #pragma unroll
        for (int nj = 0; nj < 8; ++nj)
            #pragma unroll
            for (int q = 0; q < 4; ++q) d[mi][nj][q] = 0.f;

    gemm_phase<8, false>(sbase, OFF_W2THI, OFF_W2TLO, OFF_HHI, OFF_HLO, wr, wc, lane, d);
    __syncthreads();   // done reading W2T before S^T overwrites it

    // Epilogue 2: +b2[row k], split -> S^T
    #pragma unroll
    for (int mi = 0; mi < 2; ++mi) {
        #pragma unroll
        for (int nj = 0; nj < 8; ++nj) {
            int col = 64 * wc + 8 * nj + c_base;
            #pragma unroll
            for (int h = 0; h < 2; ++h) {
                int row = 32 * wr + 16 * mi + r_base + 8 * h;   // row = k
                float bias = sB2[row];
                float f0 = d[mi][nj][2 * h]     + bias;
                float f1 = d[mi][nj][2 * h + 1] + bias;
                __nv_bfloat16 h0,l0,h1,l1; split_bf(f0,h0,l0); split_bf(f1,h1,l1);
                store_pair(dyn, OFF_STHI + k128_off(row, col), h0, h1);
                store_pair(dyn, OFF_STLO + k128_off(row, col), l0, l1);
            }
        }
    }
    __syncthreads();

    // ---------------- Phase 3: D3[i][k] = main @ S (B = S^T) ----------------
    #pragma unroll
    for (int mi = 0; mi < 2; ++mi)
        #pragma unroll
        for (int nj = 0; nj < 8; ++nj)
            #pragma unroll
            for (int q = 0; q < 4; ++q) d[mi][nj][q] = 0.f;

    gemm_phase<8, false>(sbase, OFF_MHI, OFF_MLO, OFF_STHI, OFF_STLO, wr, wc, lane, d);
    __syncthreads();   // done reading M tiles before staging overwrites them

    // Epilogue 3: stage fp32 into padded SMEM (stride 132), then coalesced store
    float* sOut = (float*)(dyn + OFF_OUT);
    #pragma unroll
    for (int mi = 0; mi < 2; ++mi) {
        #pragma unroll
        for (int nj = 0; nj < 8; ++nj) {
            int col = 64 * wc + 8 * nj + c_base;
            #pragma unroll
            for (int h = 0; h < 2; ++h) {
                int row = 32 * wr + 16 * mi + r_base + 8 * h;
                float2 v; v.x = d[mi][nj][2 * h]; v.y = d[mi][nj][2 * h + 1];
                *(float2*)&sOut[row * 132 + col] = v;
            }
        }
    }
    __syncthreads();

    float* outT = out + (size_t)t * 16384;
    #pragma unroll
    for (int i = 0; i < 64; i++) {
        int e = tid + i * TPB;
        outT[e] = sOut[(e >> 7) * 132 + (e & 127)];
    }
}

extern "C" void kernel_launch(void* const* d_in, const int* in_sizes, int n_in,
                              void* d_out, int out_size)
{
    const float* x_main = (const float*)d_in[0];
    const float* x_aux  = (const float*)d_in[1];
    const float* W1     = (const float*)d_in[2];
    const float* b1     = (const float*)d_in[3];
    const float* W2     = (const float*)d_in[4];
    const float* b2     = (const float*)d_in[5];
    float* out = (float*)d_out;

    cudaFuncSetAttribute(slam_mma, cudaFuncAttributeMaxDynamicSharedMemorySize, DYN_BYTES);
    slam_mma<<<1024, TPB, DYN_BYTES>>>(x_main, x_aux, W1, b1, W2, b2, out);
}